// round 16
// baseline (speedup 1.0000x reference)
#include <cuda_runtime.h>
#include <stdint.h>

// PureAEVComputer radial AEV, fused kernel (R14 champion structure),
// f32x2-packed anchor-chain accumulation, clamp-based cutoff masking
// (fminf/fmaxf, no predicates).

#define NB 4
#define NN 1024
#define PAD 1280
#define OUTW 1008
#define RCF 5.2f
#define PI_OVER_RC 0.6041524334f
#define LLCF 23.083120654223414f      // eta * log2(e), eta=16
#define KPF  12.407177351645084f      // 2 * LLC * 0.26875
#define SA 1.70625f
#define SB 3.85625f
#define T1C   0.31486064f
#define T4C   0.009828185f
#define T9C   3.0413467e-5f
#define T16C  9.3302500e-9f
#define IT16C 1.0717934e8f

typedef unsigned long long u64;

__device__ __forceinline__ float ex2a(float x) {
    float r; asm("ex2.approx.f32 %0, %1;" : "=f"(r) : "f"(x)); return r;
}
__device__ __forceinline__ float rsqa(float x) {
    float r; asm("rsqrt.approx.f32 %0, %1;" : "=f"(r) : "f"(x)); return r;
}
__device__ __forceinline__ u64 pk2(float lo, float hi) {
    u64 r; asm("mov.b64 %0, {%1, %2};" : "=l"(r) : "f"(lo), "f"(hi)); return r;
}
__device__ __forceinline__ void upk2(float& lo, float& hi, u64 v) {
    asm("mov.b64 {%0, %1}, %2;" : "=f"(lo), "=f"(hi) : "l"(v));
}
__device__ __forceinline__ u64 mul2(u64 a, u64 b) {
    u64 r; asm("mul.rn.f32x2 %0, %1, %2;" : "=l"(r) : "l"(a), "l"(b)); return r;
}
__device__ __forceinline__ u64 add2(u64 a, u64 b) {
    u64 r; asm("add.rn.f32x2 %0, %1, %2;" : "=l"(r) : "l"(a), "l"(b)); return r;
}
__device__ __forceinline__ u64 fma2(u64 a, u64 b, u64 c) {
    u64 r; asm("fma.rn.f32x2 %0, %1, %2, %3;" : "=l"(r) : "l"(a), "l"(b), "l"(c)); return r;
}

__global__ void __launch_bounds__(256, 5)
aev_fused(const int* __restrict__ spw, const float* __restrict__ coords,
          float* __restrict__ out) {
    __shared__ float4        sco[PAD];
    __shared__ unsigned char sspb[NN];
    __shared__ int           wcnt[8][4];
    __shared__ int           woff[8][4];
    __shared__ int           sbase[5];
    __shared__ int           sbad;

    const int tid  = threadIdx.x;
    const int w    = tid >> 5;
    const int lane = tid & 31;
    const int b      = blockIdx.x >> 8;        // 256 blocks per batch
    const int rowblk = blockIdx.x & 255;       // 4 rows per block
    const unsigned full = 0xffffffffu;

    if (tid == 0) sbad = 0;
    for (int t = tid; t < PAD; t += 256)
        sco[t] = make_float4(1e9f, 1e9f, 1e9f, 0.f);
    __syncthreads();

    // ---- detect int64 vs int32 ----
    int bad = 0;
    for (int q = tid; q < 512; q += 256) {
        int lo = spw[2 * q], hi = spw[2 * q + 1];
        if (hi != 0 || ((unsigned)lo) > 3u) bad = 1;
    }
    if (bad) atomicOr(&sbad, 1);
    __syncthreads();
    const int is64 = !sbad;

    for (int e = tid; e < NN; e += 256) {
        int sp = is64 ? spw[2 * (b * NN + e)] : spw[b * NN + e];
        sspb[e] = (unsigned char)sp;
    }
    __syncthreads();

    // ---- per-warp histogram ----
    {
        int c0 = 0, c1 = 0, c2 = 0, c3 = 0;
        for (int it = 0; it < 4; ++it) {
            int sp = sspb[w * 128 + it * 32 + lane];
            c0 += __popc(__ballot_sync(full, sp == 0));
            c1 += __popc(__ballot_sync(full, sp == 1));
            c2 += __popc(__ballot_sync(full, sp == 2));
            c3 += __popc(__ballot_sync(full, sp == 3));
        }
        if (lane == 0) {
            wcnt[w][0] = c0; wcnt[w][1] = c1; wcnt[w][2] = c2; wcnt[w][3] = c3;
        }
    }
    __syncthreads();

    if (tid == 0) {
        int basep = 0;
        for (int s = 0; s < 4; ++s) {
            sbase[s] = basep;
            int tot = 0;
            for (int ww = 0; ww < 8; ++ww) { woff[ww][s] = basep + tot; tot += wcnt[ww][s]; }
            basep += (tot + 31) & ~31;
        }
        sbase[4] = basep;
    }
    __syncthreads();

    // ---- scatter coords ----
    {
        const unsigned lt = (1u << lane) - 1u;
        int u0 = 0, u1 = 0, u2 = 0, u3 = 0;
        for (int it = 0; it < 4; ++it) {
            int e  = w * 128 + it * 32 + lane;
            int sp = sspb[e];
            unsigned m0 = __ballot_sync(full, sp == 0);
            unsigned m1 = __ballot_sync(full, sp == 1);
            unsigned m2 = __ballot_sync(full, sp == 2);
            unsigned m3 = __ballot_sync(full, sp == 3);
            int pos;
            if (sp == 0)      pos = woff[w][0] + u0 + __popc(m0 & lt);
            else if (sp == 1) pos = woff[w][1] + u1 + __popc(m1 & lt);
            else if (sp == 2) pos = woff[w][2] + u2 + __popc(m2 & lt);
            else              pos = woff[w][3] + u3 + __popc(m3 & lt);
            const float* cp = coords + (size_t)(b * NN + e) * 3;
            sco[pos] = make_float4(cp[0], cp[1], cp[2], 0.f);
            u0 += __popc(m0); u1 += __popc(m1); u2 += __popc(m2); u3 += __popc(m3);
        }
    }
    __syncthreads();

    // ---- zero output tails for the 4 rows ----
    {
        const float4 z4 = make_float4(0.f, 0.f, 0.f, 0.f);
        for (int r = 0; r < 4; ++r) {
            float4* o4 = (float4*)(out + (size_t)(b * NN + rowblk * 4 + r) * OUTW);
            for (int c = 16 + tid; c < 252; c += 256) o4[c] = z4;
        }
    }

    // =================== main compute ===================
    const int i  = rowblk * 4 + (w >> 1);
    const int s0 = (w & 1) * 2;

    const float* cc = coords + (size_t)(b * NN + i) * 3;
    const float xi = cc[0], yi = cc[1], zi = cc[2];
    float* orow = out + (size_t)(b * NN + i) * OUTW;

    const int b0 = lane & 1, b1 = (lane >> 1) & 1, b2 = (lane >> 2) & 1,
              b3 = (lane >> 3) & 1;

    const u64 cT1  = pk2(T1C,  T1C);
    const u64 cT4  = pk2(T4C,  T4C);
    const u64 cT9  = pk2(T9C,  T9C);
    const u64 cT16 = pk2(T16C, T16C);

#pragma unroll
    for (int ss = 0; ss < 2; ++ss) {
        const int s = s0 + ss;
        // packed acc: [0..3]=up m=1..4 shells (4,12)(5,13)(6,14)(7,15)
        //             [4..6]=down m=1..3 shells (2,10)(1,9)(0,8)
        //             [7]=anchors (3,11)
        u64 acc2[8];
#pragma unroll
        for (int k = 0; k < 8; ++k) acc2[k] = 0ull;

        const int st = sbase[s], en = sbase[s + 1];
        for (int t = st + lane; t < en; t += 32) {
            float4 cj = sco[t];
            float dx = xi - cj.x, dy = yi - cj.y, dz = zi - cj.z;
            float d2 = fmaf(dx, dx, fmaf(dy, dy, dz * dz));
            float d  = d2 * rsqa(d2);              // NaN at d2==0
            float dm = fminf(d, RCF);              // NaN/far -> 5.2 (fc -> 0)
            float fc = fmaxf(fmaf(0.5f, __cosf(dm * PI_OVER_RC), 0.5f), 0.f);

            float fa = dm - SA;
            float ga = ex2a((-LLCF * fa) * fa);
            float fb = dm - SB;
            float gb = ex2a((-LLCF * fb) * fb);
            float pa = ex2a(fmaf(KPF, dm, -KPF * SA));
            float qa = ex2a(fmaf(-KPF, dm, KPF * SA));
            float pb = pa * T16C;
            float qb = qa * IT16C;

            u64 hAB = mul2(pk2(ga, gb), pk2(fc, fc));   // (hA, hB)
            u64 up  = pk2(pa, pb);
            u64 dn  = pk2(qa, qb);

            acc2[7] = add2(acc2[7], hAB);
            u64 h = mul2(hAB, up);
            acc2[0] = fma2(h, cT1,  acc2[0]); h = mul2(h, up);
            acc2[1] = fma2(h, cT4,  acc2[1]); h = mul2(h, up);
            acc2[2] = fma2(h, cT9,  acc2[2]); h = mul2(h, up);
            acc2[3] = fma2(h, cT16, acc2[3]);
            h = mul2(hAB, dn);
            acc2[4] = fma2(h, cT1,  acc2[4]); h = mul2(h, dn);
            acc2[5] = fma2(h, cT4,  acc2[5]); h = mul2(h, dn);
            acc2[6] = fma2(h, cT9,  acc2[6]);
        }

        // unpack to scalar shell accumulators
        float acc[16];
        upk2(acc[3],  acc[11], acc2[7]);
        upk2(acc[4],  acc[12], acc2[0]);
        upk2(acc[5],  acc[13], acc2[1]);
        upk2(acc[6],  acc[14], acc2[2]);
        upk2(acc[7],  acc[15], acc2[3]);
        upk2(acc[2],  acc[10], acc2[4]);
        upk2(acc[1],  acc[9],  acc2[5]);
        upk2(acc[0],  acc[8],  acc2[6]);

        // ---- shell-distributing butterfly reduction ----
        float v[8];
#pragma unroll
        for (int j = 0; j < 8; ++j) {
            float snd = b0 ? acc[2 * j] : acc[2 * j + 1];
            float rcv = __shfl_xor_sync(full, snd, 1);
            v[j] = (b0 ? acc[2 * j + 1] : acc[2 * j]) + rcv;
        }
        float vv[4];
#pragma unroll
        for (int j = 0; j < 4; ++j) {
            float snd = b1 ? v[2 * j] : v[2 * j + 1];
            float rcv = __shfl_xor_sync(full, snd, 2);
            vv[j] = (b1 ? v[2 * j + 1] : v[2 * j]) + rcv;
        }
        float x0, x1;
        {
            float snd = b2 ? vv[0] : vv[1];
            float rcv = __shfl_xor_sync(full, snd, 4);
            x0 = (b2 ? vv[1] : vv[0]) + rcv;
            snd = b2 ? vv[2] : vv[3];
            rcv = __shfl_xor_sync(full, snd, 4);
            x1 = (b2 ? vv[3] : vv[2]) + rcv;
        }
        float y;
        {
            float snd = b3 ? x0 : x1;
            float rcv = __shfl_xor_sync(full, snd, 8);
            y = (b3 ? x1 : x0) + rcv;
        }
        y += __shfl_xor_sync(full, y, 16);

        if (lane < 16) orow[s * 16 + lane] = y;
    }
}

extern "C" void kernel_launch(void* const* d_in, const int* in_sizes, int n_in,
                              void* d_out, int out_size) {
    (void)in_sizes; (void)n_in; (void)out_size;
    const int*   spec   = (const int*)d_in[0];
    const float* coords = (const float*)d_in[1];
    float*       out    = (float*)d_out;

    aev_fused<<<NB * (NN / 4), 256>>>(spec, coords, out);
}